// round 4
// baseline (speedup 1.0000x reference)
#include <cuda_runtime.h>

#define BS   2048
#define SEQ  288
#define TST  288
#define HID  64
#define DSZ  29
#define NTHR 256

typedef unsigned long long u64;

__device__ __forceinline__ u64 pk2(float x, float y) {
    u64 r; asm("mov.b64 %0,{%1,%2};" : "=l"(r) : "f"(x), "f"(y)); return r;
}
__device__ __forceinline__ void upk2(u64 v, float& x, float& y) {
    asm("mov.b64 {%0,%1},%2;" : "=f"(x), "=f"(y) : "l"(v));
}
__device__ __forceinline__ u64 ffma2(u64 a, u64 b, u64 c) {
    u64 d; asm("fma.rn.f32x2 %0,%1,%2,%3;" : "=l"(d) : "l"(a), "l"(b), "l"(c)); return d;
}
__device__ __forceinline__ u64 fadd2(u64 a, u64 b) {
    u64 d; asm("add.rn.f32x2 %0,%1,%2;" : "=l"(d) : "l"(a), "l"(b)); return d;
}

// SMEM layout (float offsets)
#define H_OFF    0        // 2 x 64 double buffer
#define CTX_OFF  128      // 2 x 64 double buffer
#define X_OFF    256      // 2 x 32 double buffer
#define WK_OFF   320      // 64
#define BK_OFF   384      // 8
#define WHH_OFF  392      // 8 heads * 24 rows * pitch 68
#define WHH_PITCH 68
#define SMEM_FLOATS (WHH_OFF + 8 * 24 * WHH_PITCH)

__global__ __launch_bounds__(NTHR, 1)
void decoder_persist_kernel(const float* __restrict__ xdec,
                            const float* __restrict__ enc,
                            const float* __restrict__ hid,
                            const float* __restrict__ Wih,
                            const float* __restrict__ Whh,
                            const float* __restrict__ bih,
                            const float* __restrict__ bhh,
                            const float* __restrict__ Wk,
                            const float* __restrict__ bk,
                            const float* __restrict__ W1,
                            const float* __restrict__ b1,
                            const float* __restrict__ W2,
                            const float* __restrict__ b2,
                            float* __restrict__ out)
{
    extern __shared__ float sm[];
    const int tid  = threadIdx.x;
    const int warp = tid >> 5;      // == head
    const int lane = tid & 31;
    const int b    = blockIdx.x;
    const unsigned FULL = 0xffffffffu;

    // ---- register-resident weights ----
    u64 w1r[32];     // W1 row `lane` (64 floats), all lanes
    u64 wih[14];     // Wih row cols 0..27 (lanes 0-23)
    u64 val[36];     // attention values for this head (9 x 4)
    float ba = 0.f, bb = 0.f, w28 = 0.f;
    float b1l, w2l, b2r, hp = 0.f;

    {
        const ulonglong2* wp = reinterpret_cast<const ulonglong2*>(W1 + lane * HID);
#pragma unroll
        for (int k = 0; k < 16; ++k) { ulonglong2 v = wp[k]; w1r[2*k] = v.x; w1r[2*k+1] = v.y; }
        b1l = b1[lane]; w2l = W2[lane]; b2r = b2[0];
    }
    if (lane < 24) {
        const int R = 64 * (lane >> 3) + warp * 8 + (lane & 7);
        const float* wr = Wih + R * DSZ;
#pragma unroll
        for (int k = 0; k < 14; ++k) wih[k] = pk2(wr[2*k], wr[2*k+1]);
        ba = bih[R]; bb = bhh[R]; w28 = wr[28];
    }
    if (lane < 8) hp = hid[(size_t)b * HID + warp * 8 + lane];

#pragma unroll
    for (int i = 0; i < 9; ++i) {
        int s = lane + (i << 5);
        const ulonglong2* vp = reinterpret_cast<const ulonglong2*>(
            enc + ((size_t)s * BS + b) * HID + warp * 8);
        ulonglong2 v0 = vp[0], v1 = vp[1];
        val[4*i+0] = v0.x; val[4*i+1] = v0.y; val[4*i+2] = v1.x; val[4*i+3] = v1.y;
    }

    // ---- SMEM init ----
    // Whh rows regrouped: slot = head*24 + (g*8+m) for global row R = 64g + head*8 + m
    for (int idx = tid; idx < 192 * 64; idx += NTHR) {
        int R = idx >> 6, k = idx & 63;
        int g = R >> 6, rem = R & 63;
        int hh = rem >> 3, m = rem & 7;
        sm[WHH_OFF + (hh * 24 + g * 8 + m) * WHH_PITCH + k] = Whh[idx];
    }
    if (tid < 64) sm[H_OFF + tid] = hid[(size_t)b * HID + tid];   // buffer 0
    if (tid < 28) sm[X_OFF + tid] = xdec[(size_t)b * (TST + 1) * DSZ + tid];
    if (tid < 64) sm[WK_OFF + tid] = Wk[tid];
    if (tid < 8)  sm[BK_OFF + tid] = bk[tid];
    const float o0 = xdec[(size_t)b * (TST + 1) * DSZ + 28];

    float xv_pre = 0.f;
    if (warp == 7 && lane < 28)
        xv_pre = xdec[((size_t)b * (TST + 1) + 1) * DSZ + lane];

    __syncthreads();

#pragma unroll 1
    for (int t = 0; t < TST; ++t) {
        const int cur = t & 1, nxt = cur ^ 1;

        // ---- output MLP for step t-1 (redundant in every warp) ----
        float o;
        if (t == 0) {
            o = o0;
        } else {
            const ulonglong2* cp = reinterpret_cast<const ulonglong2*>(&sm[CTX_OFF + cur * 64]);
            u64 m0 = pk2(b1l, 0.f), m1 = 0ull, m2 = 0ull, m3 = 0ull;
#pragma unroll
            for (int k = 0; k < 16; k += 2) {
                ulonglong2 cA = cp[k], cB = cp[k+1];
                m0 = ffma2(w1r[2*k],   cA.x, m0);
                m1 = ffma2(w1r[2*k+1], cA.y, m1);
                m2 = ffma2(w1r[2*k+2], cB.x, m2);
                m3 = ffma2(w1r[2*k+3], cB.y, m3);
            }
            u64 ms = fadd2(fadd2(m0, m1), fadd2(m2, m3));
            float y0, y1; upk2(ms, y0, y1);
            float p = fmaxf(y0 + y1, 0.f) * w2l;
#pragma unroll
            for (int off = 16; off >= 1; off >>= 1)
                p += __shfl_xor_sync(FULL, p, off);
            o = p + b2r;
            if (warp == 0 && lane == 0) out[(size_t)b * TST + (t - 1)] = o;
        }

        // ---- GRU gate dots for own head (lanes 0-23; lane = g*8+m) ----
        float axs = 0.f, ahs = 0.f;
        if (lane < 24) {
            const u64* xp = reinterpret_cast<const u64*>(&sm[X_OFF + cur * 32]);
            u64 x0 = pk2(ba, 0.f), x1 = 0ull;
#pragma unroll
            for (int k = 0; k < 14; k += 2) {
                x0 = ffma2(wih[k],   xp[k],   x0);
                x1 = ffma2(wih[k+1], xp[k+1], x1);
            }
            const ulonglong2* wp = reinterpret_cast<const ulonglong2*>(
                &sm[WHH_OFF + (warp * 24 + lane) * WHH_PITCH]);
            const ulonglong2* hh = reinterpret_cast<const ulonglong2*>(&sm[H_OFF + cur * 64]);
            u64 h0 = pk2(bb, 0.f), h1 = 0ull, h2 = 0ull, h3 = 0ull;
#pragma unroll
            for (int k = 0; k < 16; k += 2) {
                ulonglong2 wA = wp[k], wB = wp[k+1];
                ulonglong2 hA = hh[k], hB = hh[k+1];
                h0 = ffma2(wA.x, hA.x, h0);
                h1 = ffma2(wA.y, hA.y, h1);
                h2 = ffma2(wB.x, hB.x, h2);
                h3 = ffma2(wB.y, hB.y, h3);
            }
            u64 xs = fadd2(x0, x1);
            u64 hs = fadd2(fadd2(h0, h1), fadd2(h2, h3));
            float a0, a1, c0, c1;
            upk2(xs, a0, a1); upk2(hs, c0, c1);
            axs = fmaf(w28, o, a0 + a1);
            ahs = c0 + c1;
        }

        // ---- gate exchange + nonlinearity (lanes 0-7) ----
        float gsum = axs + ahs;
        float szz = __shfl_sync(FULL, gsum, (lane + 8)  & 31);
        float axn = __shfl_sync(FULL, axs,  (lane + 16) & 31);
        float ahn = __shfl_sync(FULL, ahs,  (lane + 16) & 31);
        float hn = 0.f;
        if (lane < 8) {
            float r  = 1.f / (1.f + __expf(-gsum));
            float z  = 1.f / (1.f + __expf(-szz));
            float a  = axn + r * ahn;
            float e2 = __expf(2.f * a);
            float nt = 1.f - 2.f / (e2 + 1.f);
            hn = nt + z * (hp - nt);
            hp = hn;
            sm[H_OFF + nxt * 64 + warp * 8 + lane] = hn;
        }

        // ---- x prefetch for step t+1 (warp 7) ----
        if (warp == 7 && lane < 28) {
            sm[X_OFF + nxt * 32 + lane] = xv_pre;
            int row = (t + 2 <= TST) ? (t + 2) : TST;
            xv_pre = xdec[((size_t)b * (TST + 1) + row) * DSZ + lane];
        }

        // ---- q = h_new @ Wk (+ bk dot on lane 8) ----
        float q = 0.f;
#pragma unroll
        for (int d = 0; d < 8; ++d) {
            float hv = __shfl_sync(FULL, hn, d);
            float w  = (lane < 8) ? sm[WK_OFF + d * 8 + lane]
                     : ((lane == 8) ? sm[BK_OFF + d] : 0.f);
            q = fmaf(hv, w, q);
        }
        u64 qp2[4];
#pragma unroll
        for (int j = 0; j < 4; ++j)
            qp2[j] = pk2(__shfl_sync(FULL, q, 2 * j), __shfl_sync(FULL, q, 2 * j + 1));
        float qb = __shfl_sync(FULL, q, 8);

        // ---- single-pass attention over register-resident val ----
        float w0 = 0.f, w1s = 0.f;
        u64 c2[4] = {0ull, 0ull, 0ull, 0ull};
#pragma unroll
        for (int i = 0; i < 9; ++i) {
            u64 v0 = val[4*i+0], v1 = val[4*i+1], v2 = val[4*i+2], v3 = val[4*i+3];
            u64 acc = ffma2(qp2[0], v0, 0ull);
            acc = ffma2(qp2[1], v1, acc);
            acc = ffma2(qp2[2], v2, acc);
            acc = ffma2(qp2[3], v3, acc);
            float s0, s1; upk2(acc, s0, s1);
            float e = __expf(s0 + s1 + qb);
            if (i & 1) w1s += e; else w0 += e;
            u64 ee = pk2(e, e);
            c2[0] = ffma2(ee, v0, c2[0]);
            c2[1] = ffma2(ee, v1, c2[1]);
            c2[2] = ffma2(ee, v2, c2[2]);
            c2[3] = ffma2(ee, v3, c2[3]);
        }
        float wsum = w0 + w1s;
#pragma unroll
        for (int off = 16; off >= 1; off >>= 1) {
            wsum += __shfl_xor_sync(FULL, wsum, off);
#pragma unroll
            for (int j = 0; j < 4; ++j)
                c2[j] = fadd2(c2[j], __shfl_xor_sync(FULL, c2[j], off));
        }
        if (lane < 8) {
            float inv = 1.f / wsum;
            float lo, hi; upk2(c2[lane >> 1], lo, hi);
            float v = (lane & 1) ? hi : lo;
            sm[CTX_OFF + nxt * 64 + warp * 8 + lane] = v * inv;
        }

        __syncthreads();
    }

    // ---- final output MLP (step TST-1), ctx is in buffer 0 ----
    if (warp == 0) {
        const ulonglong2* cp = reinterpret_cast<const ulonglong2*>(&sm[CTX_OFF]);
        u64 m0 = pk2(b1l, 0.f), m1 = 0ull, m2 = 0ull, m3 = 0ull;
#pragma unroll
        for (int k = 0; k < 16; k += 2) {
            ulonglong2 cA = cp[k], cB = cp[k+1];
            m0 = ffma2(w1r[2*k],   cA.x, m0);
            m1 = ffma2(w1r[2*k+1], cA.y, m1);
            m2 = ffma2(w1r[2*k+2], cB.x, m2);
            m3 = ffma2(w1r[2*k+3], cB.y, m3);
        }
        u64 ms = fadd2(fadd2(m0, m1), fadd2(m2, m3));
        float y0, y1; upk2(ms, y0, y1);
        float p = fmaxf(y0 + y1, 0.f) * w2l;
#pragma unroll
        for (int off = 16; off >= 1; off >>= 1)
            p += __shfl_xor_sync(FULL, p, off);
        if (lane == 0)
            out[(size_t)b * TST + (TST - 1)] = p + b2r;
    }
}

extern "C" void kernel_launch(void* const* d_in, const int* in_sizes, int n_in,
                              void* d_out, int out_size)
{
    const float* xdec = (const float*)d_in[0];
    const float* enc  = (const float*)d_in[1];
    const float* hidp = (const float*)d_in[2];
    const float* Wih  = (const float*)d_in[3];
    const float* Whh  = (const float*)d_in[4];
    const float* bih  = (const float*)d_in[5];
    const float* bhh  = (const float*)d_in[6];
    const float* Wk   = (const float*)d_in[7];
    const float* bk   = (const float*)d_in[8];
    const float* W1   = (const float*)d_in[9];
    const float* b1   = (const float*)d_in[10];
    const float* W2   = (const float*)d_in[11];
    const float* b2   = (const float*)d_in[12];
    float* out = (float*)d_out;

    const size_t smem = SMEM_FLOATS * sizeof(float);
    cudaFuncSetAttribute(decoder_persist_kernel,
                         cudaFuncAttributeMaxDynamicSharedMemorySize, (int)smem);
    decoder_persist_kernel<<<BS, NTHR, smem>>>(xdec, enc, hidp, Wih, Whh, bih, bhh,
                                               Wk, bk, W1, b1, W2, b2, out);
}

// round 5
// speedup vs baseline: 2.1615x; 2.1615x over previous
#include <cuda_runtime.h>

#define BS   2048
#define SEQ  288
#define TST  288
#define HID  64
#define DSZ  29
#define NTHR 256
#define VPITCH 68   // floats per val row: conflict-free LDS.128 across lanes

typedef unsigned long long u64;

__device__ __forceinline__ u64 pk2(float x, float y) {
    u64 r; asm("mov.b64 %0,{%1,%2};" : "=l"(r) : "f"(x), "f"(y)); return r;
}
__device__ __forceinline__ void upk2(u64 v, float& x, float& y) {
    asm("mov.b64 {%0,%1},%2;" : "=f"(x), "=f"(y) : "l"(v));
}
__device__ __forceinline__ u64 ffma2(u64 a, u64 b, u64 c) {
    u64 d; asm("fma.rn.f32x2 %0,%1,%2,%3;" : "=l"(d) : "l"(a), "l"(b), "l"(c)); return d;
}
__device__ __forceinline__ u64 fadd2(u64 a, u64 b) {
    u64 d; asm("add.rn.f32x2 %0,%1,%2;" : "=l"(d) : "l"(a), "l"(b)); return d;
}

// SMEM layout (float offsets)
#define GS_OFF   0      // 128: gx+gh presummed, r rows [0,64), z rows [64,128)
#define GXN_OFF  128    // 64: gx for n rows
#define GHN_OFF  192    // 64: gh for n rows
#define H_OFF    256    // 64
#define X_OFF    320    // 2 x 32 double buffer
#define CTX_OFF  384    // 64
#define OUTS_OFF 448
#define WIH_OFF  452    // 192 rows x 30 floats (cols 0..27 used; u64-aligned)
#define VAL_OFF  6212   // 288 x 68
#define SMEM_FLOATS (VAL_OFF + SEQ * VPITCH)

__global__ __launch_bounds__(NTHR, 2)
void decoder_persist_kernel(const float* __restrict__ xdec,
                            const float* __restrict__ enc,
                            const float* __restrict__ hid,
                            const float* __restrict__ Wih,
                            const float* __restrict__ Whh,
                            const float* __restrict__ bih,
                            const float* __restrict__ bhh,
                            const float* __restrict__ Wk,
                            const float* __restrict__ bk,
                            const float* __restrict__ W1,
                            const float* __restrict__ b1,
                            const float* __restrict__ W2,
                            const float* __restrict__ b2,
                            float* __restrict__ out)
{
    extern __shared__ float sm[];
    const int tid  = threadIdx.x;
    const int warp = tid >> 5;      // head id in phase C
    const int lane = tid & 31;
    const int b    = blockIdx.x;
    const unsigned FULL = 0xffffffffu;

    // ---- register-resident constants ----
    u64 wreg[32];                 // Whh row (tid<192) OR W1 row (warp 6)
    float wk[8];                  // Wk column (lanes 0-7) / bk (lane 8) / 0
    float w28r = 0.f, w28z = 0.f, w28n = 0.f;
    float ba = 0.f, bb = 0.f, b2r = 0.f;

    if (tid < 192) {
        const ulonglong2* wp = reinterpret_cast<const ulonglong2*>(Whh + tid * HID);
#pragma unroll
        for (int k = 0; k < 16; ++k) { ulonglong2 v = wp[k]; wreg[2*k] = v.x; wreg[2*k+1] = v.y; }
        ba = bih[tid]; bb = bhh[tid];
    } else if (warp == 6) {
        const ulonglong2* wp = reinterpret_cast<const ulonglong2*>(W1 + lane * HID);
#pragma unroll
        for (int k = 0; k < 16; ++k) { ulonglong2 v = wp[k]; wreg[2*k] = v.x; wreg[2*k+1] = v.y; }
        ba = b1[lane]; bb = W2[lane]; b2r = b2[0];
    }
#pragma unroll
    for (int d = 0; d < 8; ++d)
        wk[d] = (lane < 8) ? Wk[d * 8 + lane] : ((lane == 8) ? bk[d] : 0.f);
    if (lane < 8) {
        const int i = warp * 8 + lane;
        w28r = Wih[i * DSZ + 28];
        w28z = Wih[(64 + i) * DSZ + 28];
        w28n = Wih[(128 + i) * DSZ + 28];
    }

    // ---- SMEM init ----
    for (int idx = tid; idx < SEQ * (HID/4); idx += NTHR) {   // val, pitch 68
        int s = idx >> 4, c4 = idx & 15;
        float4 v = reinterpret_cast<const float4*>(enc + ((size_t)s * BS + b) * HID)[c4];
        *reinterpret_cast<float4*>(&sm[VAL_OFF + s * VPITCH + 4 * c4]) = v;
    }
    for (int idx = tid; idx < 192 * 28; idx += NTHR) {        // Wih cols 0..27, stride 30
        int row = idx / 28, k = idx - row * 28;
        sm[WIH_OFF + row * 30 + k] = Wih[row * DSZ + k];
    }
    if (tid < HID) sm[H_OFF + tid] = hid[(size_t)b * HID + tid];
    if (tid < 28)  sm[X_OFF + tid] = xdec[(size_t)b * (TST + 1) * DSZ + tid];
    if (tid == 0)  sm[OUTS_OFF] = xdec[(size_t)b * (TST + 1) * DSZ + 28];

    float xv_pre = 0.f;
    if (warp == 7 && lane < 28)
        xv_pre = xdec[((size_t)b * (TST + 1) + 1) * DSZ + lane];

    __syncthreads();

#pragma unroll 1
    for (int t = 0; t < TST; ++t) {
        const int cur = t & 1, nxt = cur ^ 1;

        // ======== PHASE A: GRU dots (w0-5) | MLP t-1 (w6) | prefetch (w7) ========
        if (tid < 192) {
            const int g = tid >> 6, j = tid & 63;
            u64 ax0 = pk2(ba, 0.f), ax1 = 0ull;
            const u64* xp = reinterpret_cast<const u64*>(&sm[X_OFF + cur * 32]);
            const u64* wp = reinterpret_cast<const u64*>(&sm[WIH_OFF + tid * 30]);
#pragma unroll
            for (int k = 0; k < 14; k += 2) {
                ax0 = ffma2(wp[k],   xp[k],   ax0);
                ax1 = ffma2(wp[k+1], xp[k+1], ax1);
            }
            u64 ah0 = pk2(bb, 0.f), ah1 = 0ull, ah2 = 0ull, ah3 = 0ull;
            const ulonglong2* hp4 = reinterpret_cast<const ulonglong2*>(&sm[H_OFF]);
#pragma unroll
            for (int k = 0; k < 16; k += 2) {
                ulonglong2 hA = hp4[k], hB = hp4[k+1];
                ah0 = ffma2(wreg[2*k],   hA.x, ah0);
                ah1 = ffma2(wreg[2*k+1], hA.y, ah1);
                ah2 = ffma2(wreg[2*k+2], hB.x, ah2);
                ah3 = ffma2(wreg[2*k+3], hB.y, ah3);
            }
            u64 xs = fadd2(ax0, ax1);
            u64 hs = fadd2(fadd2(ah0, ah1), fadd2(ah2, ah3));
            float a0, a1, c0, c1;
            upk2(xs, a0, a1); upk2(hs, c0, c1);
            float gxs = a0 + a1, ghs = c0 + c1;
            if (g < 2) sm[GS_OFF + (g << 6) + j] = gxs + ghs;
            else { sm[GXN_OFF + j] = gxs; sm[GHN_OFF + j] = ghs; }
        } else if (warp == 6) {
            if (t > 0) {
                u64 m0 = pk2(ba, 0.f), m1 = 0ull, m2 = 0ull, m3 = 0ull;
                const ulonglong2* cp = reinterpret_cast<const ulonglong2*>(&sm[CTX_OFF]);
#pragma unroll
                for (int k = 0; k < 16; k += 2) {
                    ulonglong2 cA = cp[k], cB = cp[k+1];
                    m0 = ffma2(wreg[2*k],   cA.x, m0);
                    m1 = ffma2(wreg[2*k+1], cA.y, m1);
                    m2 = ffma2(wreg[2*k+2], cB.x, m2);
                    m3 = ffma2(wreg[2*k+3], cB.y, m3);
                }
                u64 ms = fadd2(fadd2(m0, m1), fadd2(m2, m3));
                float y0, y1; upk2(ms, y0, y1);
                float p = fmaxf(y0 + y1, 0.f) * bb;
#pragma unroll
                for (int off = 16; off >= 1; off >>= 1)
                    p += __shfl_xor_sync(FULL, p, off);
                if (lane == 0) {
                    float o = p + b2r;
                    out[(size_t)b * TST + (t - 1)] = o;
                    sm[OUTS_OFF] = o;
                }
            }
        } else if (warp == 7) {
            if (lane < 28) {
                sm[X_OFF + nxt * 32 + lane] = xv_pre;
                int row = (t + 2 <= TST) ? (t + 2) : TST;
                xv_pre = xdec[((size_t)b * (TST + 1) + row) * DSZ + lane];
            }
        }
        __syncthreads();

        // ======== PHASE C: gates (lanes<8) + attention (all warps, head=warp) ======
        {
            float hn = 0.f;
            if (lane < 8) {
                const int i = warp * 8 + lane;
                float o  = sm[OUTS_OFF];
                float gr = sm[GS_OFF + i]      + w28r * o;
                float gz = sm[GS_OFF + 64 + i] + w28z * o;
                float ax = sm[GXN_OFF + i]     + w28n * o;
                float ah = sm[GHN_OFF + i];
                float r  = 1.f / (1.f + __expf(-gr));
                float z  = 1.f / (1.f + __expf(-gz));
                float a  = ax + r * ah;
                float e2 = __expf(2.f * a);
                float nt = 1.f - 2.f / (e2 + 1.f);
                float hp0 = sm[H_OFF + i];
                hn = nt + z * (hp0 - nt);
                sm[H_OFF + i] = hn;
            }

            // q' = h_new @ Wk (lanes 0-7), qb = h_new . bk (lane 8)
            float q = 0.f;
#pragma unroll
            for (int d = 0; d < 8; ++d)
                q = fmaf(__shfl_sync(FULL, hn, d), wk[d], q);
            u64 qp2[4];
#pragma unroll
            for (int j = 0; j < 4; ++j)
                qp2[j] = pk2(__shfl_sync(FULL, q, 2 * j), __shfl_sync(FULL, q, 2 * j + 1));
            float qb = __shfl_sync(FULL, q, 8);

            // single-pass attention over SMEM val
            float w0 = 0.f, w1s = 0.f;
            u64 c2[4] = {0ull, 0ull, 0ull, 0ull};
            const float* vb = &sm[VAL_OFF + warp * 8];
#pragma unroll
            for (int i = 0; i < 9; ++i) {
                const ulonglong2* vp = reinterpret_cast<const ulonglong2*>(
                    vb + (lane + (i << 5)) * VPITCH);
                ulonglong2 vA = vp[0], vB = vp[1];
                u64 acc = ffma2(qp2[0], vA.x, 0ull);
                acc = ffma2(qp2[1], vA.y, acc);
                acc = ffma2(qp2[2], vB.x, acc);
                acc = ffma2(qp2[3], vB.y, acc);
                float s0, s1; upk2(acc, s0, s1);
                float e = __expf(s0 + s1 + qb);
                if (i & 1) w1s += e; else w0 += e;
                u64 ee = pk2(e, e);
                c2[0] = ffma2(ee, vA.x, c2[0]);
                c2[1] = ffma2(ee, vA.y, c2[1]);
                c2[2] = ffma2(ee, vB.x, c2[2]);
                c2[3] = ffma2(ee, vB.y, c2[3]);
            }
            float wsum = w0 + w1s;
#pragma unroll
            for (int off = 16; off >= 1; off >>= 1) {
                wsum += __shfl_xor_sync(FULL, wsum, off);
#pragma unroll
                for (int j = 0; j < 4; ++j)
                    c2[j] = fadd2(c2[j], __shfl_xor_sync(FULL, c2[j], off));
            }
            if (lane < 8) {
                float inv = 1.f / wsum;
                float lo, hi; upk2(c2[lane >> 1], lo, hi);
                float v = (lane & 1) ? hi : lo;
                sm[CTX_OFF + warp * 8 + lane] = v * inv;
            }
        }
        __syncthreads();
    }

    // final output MLP (step TST-1)
    if (warp == 6) {
        u64 m0 = pk2(ba, 0.f), m1 = 0ull, m2 = 0ull, m3 = 0ull;
        const ulonglong2* cp = reinterpret_cast<const ulonglong2*>(&sm[CTX_OFF]);
#pragma unroll
        for (int k = 0; k < 16; k += 2) {
            ulonglong2 cA = cp[k], cB = cp[k+1];
            m0 = ffma2(wreg[2*k],   cA.x, m0);
            m1 = ffma2(wreg[2*k+1], cA.y, m1);
            m2 = ffma2(wreg[2*k+2], cB.x, m2);
            m3 = ffma2(wreg[2*k+3], cB.y, m3);
        }
        u64 ms = fadd2(fadd2(m0, m1), fadd2(m2, m3));
        float y0, y1; upk2(ms, y0, y1);
        float p = fmaxf(y0 + y1, 0.f) * bb;
#pragma unroll
        for (int off = 16; off >= 1; off >>= 1)
            p += __shfl_xor_sync(FULL, p, off);
        if (lane == 0)
            out[(size_t)b * TST + (TST - 1)] = p + b2r;
    }
}

extern "C" void kernel_launch(void* const* d_in, const int* in_sizes, int n_in,
                              void* d_out, int out_size)
{
    const float* xdec = (const float*)d_in[0];
    const float* enc  = (const float*)d_in[1];
    const float* hidp = (const float*)d_in[2];
    const float* Wih  = (const float*)d_in[3];
    const float* Whh  = (const float*)d_in[4];
    const float* bih  = (const float*)d_in[5];
    const float* bhh  = (const float*)d_in[6];
    const float* Wk   = (const float*)d_in[7];
    const float* bk   = (const float*)d_in[8];
    const float* W1   = (const float*)d_in[9];
    const float* b1   = (const float*)d_in[10];
    const float* W2   = (const float*)d_in[11];
    const float* b2   = (const float*)d_in[12];
    float* out = (float*)d_out;

    const size_t smem = SMEM_FLOATS * sizeof(float);
    cudaFuncSetAttribute(decoder_persist_kernel,
                         cudaFuncAttributeMaxDynamicSharedMemorySize, (int)smem);
    decoder_persist_kernel<<<BS, NTHR, smem>>>(xdec, enc, hidp, Wih, Whh, bih, bhh,
                                               Wk, bk, W1, b1, W2, b2, out);
}

// round 7
// speedup vs baseline: 2.4171x; 1.1182x over previous
#include <cuda_runtime.h>
#include <cuda_fp16.h>

#define BS   2048
#define SEQ  288
#define TST  288
#define HID  64
#define DSZ  29
#define NTHR 256

typedef unsigned long long u64;
typedef unsigned int u32;

__device__ __forceinline__ u64 pk2(float x, float y) {
    u64 r; asm("mov.b64 %0,{%1,%2};" : "=l"(r) : "f"(x), "f"(y)); return r;
}
__device__ __forceinline__ void upk2(u64 v, float& x, float& y) {
    asm("mov.b64 {%0,%1},%2;" : "=f"(x), "=f"(y) : "l"(v));
}
__device__ __forceinline__ u64 ffma2(u64 a, u64 b, u64 c) {
    u64 d; asm("fma.rn.f32x2 %0,%1,%2,%3;" : "=l"(d) : "l"(a), "l"(b), "l"(c)); return d;
}
__device__ __forceinline__ u64 fadd2(u64 a, u64 b) {
    u64 d; asm("add.rn.f32x2 %0,%1,%2;" : "=l"(d) : "l"(a), "l"(b)); return d;
}
__device__ __forceinline__ u64 shfl_u64(u64 v, int srcmask) {
    float x, y; upk2(v, x, y);
    x = __shfl_xor_sync(0xffffffffu, x, srcmask);
    y = __shfl_xor_sync(0xffffffffu, y, srcmask);
    return pk2(x, y);
}

// ---- SMEM layout ----
#define GS_OFF   0      // 128: gx+gh presummed (r rows [0,64), z rows [64,128))
#define GXN_OFF  128    // 64
#define GHN_OFF  192    // 64
#define H_OFF    256    // 64
#define X_OFF    320    // 2 x 32 double buffer
#define CTX_OFF  384    // 64
#define OUTS_OFF 448
#define FREG     456
// half regions (byte offsets)
#define WIH_B    (FREG * 4)                   // 1824 (16B aligned)
#define WIH_PH   36                           // halves per row; 72B stride
#define VAL_B    (WIH_B + 192 * WIH_PH * 2)   // 15648 (16B aligned)
#define VAL_PH   72                           // halves per row; 144B stride
#define SMEM_BYTES (VAL_B + SEQ * VAL_PH * 2) // 57120

__global__ __launch_bounds__(NTHR, 2)
void decoder_persist_kernel(const float* __restrict__ xdec,
                            const float* __restrict__ enc,
                            const float* __restrict__ hid,
                            const float* __restrict__ Wih,
                            const float* __restrict__ Whh,
                            const float* __restrict__ bih,
                            const float* __restrict__ bhh,
                            const float* __restrict__ Wk,
                            const float* __restrict__ bk,
                            const float* __restrict__ W1,
                            const float* __restrict__ b1,
                            const float* __restrict__ W2,
                            const float* __restrict__ b2,
                            float* __restrict__ out)
{
    extern __shared__ float sm[];
    char* smc = reinterpret_cast<char*>(sm);
    __half* wih_h = reinterpret_cast<__half*>(smc + WIH_B);
    __half* val_h = reinterpret_cast<__half*>(smc + VAL_B);

    const int tid  = threadIdx.x;
    const int warp = tid >> 5;      // head id in phase C
    const int lane = tid & 31;
    const int b    = blockIdx.x;
    const unsigned FULL = 0xffffffffu;

    // ---- register-resident constants ----
    u64 wreg[32];                 // Whh row (tid<192) OR W1 row (warp 6)
    float wk[8];                  // Wk column (lanes 0-7) / bk (lane 8) / 0
    float w28r = 0.f, w28z = 0.f, w28n = 0.f;
    float ba = 0.f, bb = 0.f, b2r = 0.f;

    if (tid < 192) {
        const ulonglong2* wp = reinterpret_cast<const ulonglong2*>(Whh + tid * HID);
#pragma unroll
        for (int k = 0; k < 16; ++k) { ulonglong2 v = wp[k]; wreg[2*k] = v.x; wreg[2*k+1] = v.y; }
        ba = bih[tid]; bb = bhh[tid];
    } else if (warp == 6) {
        const ulonglong2* wp = reinterpret_cast<const ulonglong2*>(W1 + lane * HID);
#pragma unroll
        for (int k = 0; k < 16; ++k) { ulonglong2 v = wp[k]; wreg[2*k] = v.x; wreg[2*k+1] = v.y; }
        ba = b1[lane]; bb = W2[lane]; b2r = b2[0];
    }
#pragma unroll
    for (int d = 0; d < 8; ++d)
        wk[d] = (lane < 8) ? Wk[d * 8 + lane] : ((lane == 8) ? bk[d] : 0.f);
    if (lane < 8) {
        const int i = warp * 8 + lane;
        w28r = Wih[i * DSZ + 28];
        w28z = Wih[(64 + i) * DSZ + 28];
        w28n = Wih[(128 + i) * DSZ + 28];
    }

    // ---- SMEM init ----
    for (int idx = tid; idx < SEQ * 16; idx += NTHR) {   // val fp16, pitch 72 halves
        int s = idx >> 4, c4 = idx & 15;
        float4 v = reinterpret_cast<const float4*>(enc + ((size_t)s * BS + b) * HID)[c4];
        __half2* dst = reinterpret_cast<__half2*>(val_h + s * VAL_PH + c4 * 4);
        dst[0] = __floats2half2_rn(v.x, v.y);
        dst[1] = __floats2half2_rn(v.z, v.w);
    }
    for (int idx = tid; idx < 192 * 28; idx += NTHR) {   // Wih fp16 cols 0..27
        int row = idx / 28, k = idx - row * 28;
        wih_h[row * WIH_PH + k] = __float2half_rn(Wih[row * DSZ + k]);
    }
    if (tid < HID) sm[H_OFF + tid] = hid[(size_t)b * HID + tid];
    if (tid < 28)  sm[X_OFF + tid] = xdec[(size_t)b * (TST + 1) * DSZ + tid];
    if (tid == 0)  sm[OUTS_OFF] = xdec[(size_t)b * (TST + 1) * DSZ + 28];

    float xv_pre = 0.f;
    if (warp == 7 && lane < 28)
        xv_pre = xdec[((size_t)b * (TST + 1) + 1) * DSZ + lane];

    __syncthreads();

#pragma unroll 1
    for (int t = 0; t < TST; ++t) {
        const int cur = t & 1, nxt = cur ^ 1;

        // ======== PHASE A: GRU dots (w0-5) | MLP t-1 (w6) | prefetch (w7) ========
        if (tid < 192) {
            const int g = tid >> 6, j = tid & 63;
            u64 ax0 = pk2(ba, 0.f), ax1 = 0ull;
            const u64*  xp = reinterpret_cast<const u64*>(&sm[X_OFF + cur * 32]);
            const uint2* wp = reinterpret_cast<const uint2*>(wih_h + tid * WIH_PH);
#pragma unroll
            for (int k = 0; k < 7; ++k) {
                uint2 w4 = wp[k];
                float2 f0 = __half22float2(*reinterpret_cast<__half2*>(&w4.x));
                float2 f1 = __half22float2(*reinterpret_cast<__half2*>(&w4.y));
                ax0 = ffma2(pk2(f0.x, f0.y), xp[2*k],   ax0);
                ax1 = ffma2(pk2(f1.x, f1.y), xp[2*k+1], ax1);
            }
            u64 ah0 = pk2(bb, 0.f), ah1 = 0ull, ah2 = 0ull, ah3 = 0ull;
            const ulonglong2* hp4 = reinterpret_cast<const ulonglong2*>(&sm[H_OFF]);
#pragma unroll
            for (int k = 0; k < 16; k += 2) {
                ulonglong2 hA = hp4[k], hB = hp4[k+1];
                ah0 = ffma2(wreg[2*k],   hA.x, ah0);
                ah1 = ffma2(wreg[2*k+1], hA.y, ah1);
                ah2 = ffma2(wreg[2*k+2], hB.x, ah2);
                ah3 = ffma2(wreg[2*k+3], hB.y, ah3);
            }
            u64 xs = fadd2(ax0, ax1);
            u64 hs = fadd2(fadd2(ah0, ah1), fadd2(ah2, ah3));
            float a0, a1, c0, c1;
            upk2(xs, a0, a1); upk2(hs, c0, c1);
            float gxs = a0 + a1, ghs = c0 + c1;
            if (g < 2) sm[GS_OFF + (g << 6) + j] = gxs + ghs;
            else { sm[GXN_OFF + j] = gxs; sm[GHN_OFF + j] = ghs; }
        } else if (warp == 6) {
            if (t > 0) {
                u64 m0 = pk2(ba, 0.f), m1 = 0ull, m2 = 0ull, m3 = 0ull;
                const ulonglong2* cp = reinterpret_cast<const ulonglong2*>(&sm[CTX_OFF]);
#pragma unroll
                for (int k = 0; k < 16; k += 2) {
                    ulonglong2 cA = cp[k], cB = cp[k+1];
                    m0 = ffma2(wreg[2*k],   cA.x, m0);
                    m1 = ffma2(wreg[2*k+1], cA.y, m1);
                    m2 = ffma2(wreg[2*k+2], cB.x, m2);
                    m3 = ffma2(wreg[2*k+3], cB.y, m3);
                }
                u64 ms = fadd2(fadd2(m0, m1), fadd2(m2, m3));
                float y0, y1; upk2(ms, y0, y1);
                float p = fmaxf(y0 + y1, 0.f) * bb;
#pragma unroll
                for (int off = 16; off >= 1; off >>= 1)
                    p += __shfl_xor_sync(FULL, p, off);
                if (lane == 0) {
                    float o = p + b2r;
                    out[(size_t)b * TST + (t - 1)] = o;
                    sm[OUTS_OFF] = o;
                }
            }
        } else if (warp == 7) {
            if (lane < 28) {
                sm[X_OFF + nxt * 32 + lane] = xv_pre;
                int row = (t + 2 <= TST) ? (t + 2) : TST;
                xv_pre = xdec[((size_t)b * (TST + 1) + row) * DSZ + lane];
            }
        }
        __syncthreads();

        // ======== PHASE C: gates (lanes<8) + attention (all warps, head=warp) ======
        {
            float hn = 0.f;
            if (lane < 8) {
                const int i = warp * 8 + lane;
                float o  = sm[OUTS_OFF];
                float gr = sm[GS_OFF + i]      + w28r * o;
                float gz = sm[GS_OFF + 64 + i] + w28z * o;
                float ax = sm[GXN_OFF + i]     + w28n * o;
                float ah = sm[GHN_OFF + i];
                float r  = 1.f / (1.f + __expf(-gr));
                float z  = 1.f / (1.f + __expf(-gz));
                float a  = ax + r * ah;
                float e2 = __expf(2.f * a);
                float nt = 1.f - 2.f / (e2 + 1.f);
                float hp0 = sm[H_OFF + i];
                hn = nt + z * (hp0 - nt);
                sm[H_OFF + i] = hn;
            }

            // q' = h_new @ Wk (lanes 0-7), qb = h_new . bk (lane 8)
            float q = 0.f;
#pragma unroll
            for (int d = 0; d < 8; ++d)
                q = fmaf(__shfl_sync(FULL, hn, d), wk[d], q);
            u64 qp2[4];
#pragma unroll
            for (int j = 0; j < 4; ++j)
                qp2[j] = pk2(__shfl_sync(FULL, q, 2 * j), __shfl_sync(FULL, q, 2 * j + 1));
            float qb = __shfl_sync(FULL, q, 8);

            // single-pass attention over fp16 val in SMEM
            float w0 = 0.f, w1s = 0.f;
            u64 c2[4] = {0ull, 0ull, 0ull, 0ull};
            const char* vb = reinterpret_cast<const char*>(val_h + warp * 8);
#pragma unroll
            for (int i = 0; i < 9; ++i) {
                uint4 vv = *reinterpret_cast<const uint4*>(
                    vb + (size_t)(lane + (i << 5)) * (VAL_PH * 2));
                float2 f0 = __half22float2(*reinterpret_cast<__half2*>(&vv.x));
                float2 f1 = __half22float2(*reinterpret_cast<__half2*>(&vv.y));
                float2 f2 = __half22float2(*reinterpret_cast<__half2*>(&vv.z));
                float2 f3 = __half22float2(*reinterpret_cast<__half2*>(&vv.w));
                u64 v0 = pk2(f0.x, f0.y), v1 = pk2(f1.x, f1.y);
                u64 v2 = pk2(f2.x, f2.y), v3 = pk2(f3.x, f3.y);
                u64 acc = ffma2(qp2[0], v0, 0ull);
                acc = ffma2(qp2[1], v1, acc);
                acc = ffma2(qp2[2], v2, acc);
                acc = ffma2(qp2[3], v3, acc);
                float s0, s1; upk2(acc, s0, s1);
                float e = __expf(s0 + s1 + qb);
                if (i & 1) w1s += e; else w0 += e;
                u64 ee = pk2(e, e);
                c2[0] = ffma2(ee, v0, c2[0]);
                c2[1] = ffma2(ee, v1, c2[1]);
                c2[2] = ffma2(ee, v2, c2[2]);
                c2[3] = ffma2(ee, v3, c2[3]);
            }
            float wsum = w0 + w1s;

            // --- reduction: 2 full butterfly stages + 3 halving stages ---
            // full stages (off 16, 8)
#pragma unroll
            for (int off = 16; off >= 8; off >>= 1) {
                wsum += __shfl_xor_sync(FULL, wsum, off);
#pragma unroll
                for (int j = 0; j < 4; ++j)
                    c2[j] = fadd2(c2[j], shfl_u64(c2[j], off));
            }
            // off=4: keep half matching lane bit2 (dims 0-3 vs 4-7)
            {
                const bool hi = (lane & 4);
                u64 s0 = hi ? c2[0] : c2[2];
                u64 s1 = hi ? c2[1] : c2[3];
                u64 r0 = shfl_u64(s0, 4);
                u64 r1 = shfl_u64(s1, 4);
                u64 k0 = hi ? c2[2] : c2[0];
                u64 k1 = hi ? c2[3] : c2[1];
                c2[0] = fadd2(k0, r0);       // dims (base, base+1)
                c2[1] = fadd2(k1, r1);       // dims (base+2, base+3)
                wsum += __shfl_xor_sync(FULL, wsum, 4);
            }
            // off=2: keep pair matching lane bit1
            {
                const bool hi = (lane & 2);
                u64 s = hi ? c2[0] : c2[1];
                u64 r = shfl_u64(s, 2);
                u64 k = hi ? c2[1] : c2[0];
                c2[0] = fadd2(k, r);         // dims (base2, base2+1)
                wsum += __shfl_xor_sync(FULL, wsum, 2);
            }
            // off=1: keep element matching lane bit0
            float ctxv;
            {
                float e0, e1; upk2(c2[0], e0, e1);
                const bool hi = (lane & 1);
                float s = hi ? e0 : e1;
                float r = __shfl_xor_sync(FULL, s, 1);
                ctxv = (hi ? e1 : e0) + r;
                wsum += __shfl_xor_sync(FULL, wsum, 1);
            }
            if (lane < 8)
                sm[CTX_OFF + warp * 8 + lane] = ctxv * (1.f / wsum);
        }
        __syncthreads();
    }

    // final output MLP (step TST-1)
    if (warp == 6) {
        u64 m0 = pk2(ba, 0.f), m1 = 0ull, m2 = 0ull, m3 = 0ull;
        const ulonglong2* cp = reinterpret_cast<const ulonglong2*>(&sm[CTX_OFF]);
#pragma unroll
        for (int k = 0; k < 16; k += 2) {
            ulonglong2 cA = cp[k], cB = cp[k+1];
            m0 = ffma2(wreg[2*k],   cA.x, m0);
            m1 = ffma2(wreg[2*k+1], cA.y, m1);
            m2 = ffma2(wreg[2*k+2], cB.x, m2);
            m3 = ffma2(wreg[2*k+3], cB.y, m3);
        }
        u64 ms = fadd2(fadd2(m0, m1), fadd2(m2, m3));
        float y0, y1; upk2(ms, y0, y1);
        float p = fmaxf(y0 + y1, 0.f) * bb;
#pragma unroll
        for (int off = 16; off >= 1; off >>= 1)
            p += __shfl_xor_sync(FULL, p, off);
        if (lane == 0)
            out[(size_t)b * TST + (TST - 1)] = p + b2r;
    }
}

extern "C" void kernel_launch(void* const* d_in, const int* in_sizes, int n_in,
                              void* d_out, int out_size)
{
    const float* xdec = (const float*)d_in[0];
    const float* enc  = (const float*)d_in[1];
    const float* hidp = (const float*)d_in[2];
    const float* Wih  = (const float*)d_in[3];
    const float* Whh  = (const float*)d_in[4];
    const float* bih  = (const float*)d_in[5];
    const float* bhh  = (const float*)d_in[6];
    const float* Wk   = (const float*)d_in[7];
    const float* bk   = (const float*)d_in[8];
    const float* W1   = (const float*)d_in[9];
    const float* b1   = (const float*)d_in[10];
    const float* W2   = (const float*)d_in[11];
    const float* b2   = (const float*)d_in[12];
    float* out = (float*)d_out;

    cudaFuncSetAttribute(decoder_persist_kernel,
                         cudaFuncAttributeMaxDynamicSharedMemorySize, SMEM_BYTES);
    decoder_persist_kernel<<<BS, NTHR, SMEM_BYTES>>>(xdec, enc, hidp, Wih, Whh, bih, bhh,
                                                     Wk, bk, W1, b1, W2, b2, out);
}

// round 8
// speedup vs baseline: 2.8691x; 1.1870x over previous
#include <cuda_runtime.h>
#include <cuda_fp16.h>

#define BS   2048
#define SEQ  288
#define TST  288
#define HID  64
#define DSZ  29
#define NTHR 256

typedef unsigned long long u64;

__device__ __forceinline__ u64 pk2(float x, float y) {
    u64 r; asm("mov.b64 %0,{%1,%2};" : "=l"(r) : "f"(x), "f"(y)); return r;
}
__device__ __forceinline__ void upk2(u64 v, float& x, float& y) {
    asm("mov.b64 {%0,%1},%2;" : "=f"(x), "=f"(y) : "l"(v));
}
__device__ __forceinline__ u64 ffma2(u64 a, u64 b, u64 c) {
    u64 d; asm("fma.rn.f32x2 %0,%1,%2,%3;" : "=l"(d) : "l"(a), "l"(b), "l"(c)); return d;
}
__device__ __forceinline__ u64 fadd2(u64 a, u64 b) {
    u64 d; asm("add.rn.f32x2 %0,%1,%2;" : "=l"(d) : "l"(a), "l"(b)); return d;
}
__device__ __forceinline__ u64 shfl_u64(u64 v, int m) {
    float x, y; upk2(v, x, y);
    x = __shfl_xor_sync(0xffffffffu, x, m);
    y = __shfl_xor_sync(0xffffffffu, y, m);
    return pk2(x, y);
}
__device__ __forceinline__ __half2 u2h2(unsigned int v) {
    return *reinterpret_cast<__half2*>(&v);
}

// ---- SMEM layout (byte offsets) ----
#define GS_B    0                         // 128 fp32: gx+gh (r rows 0-63, z rows 64-127)
#define GXN_B   512                       // 64 fp32
#define GHN_B   768                       // 64 fp32
#define H32_B   1024                      // 64 fp32
#define OUTS_B  1280                      // 1 fp32
#define XH_B    1312                      // 2 x 32 halves (double buffer)
#define HH_B    1440                      // 64 halves
#define CTXH_B  1568                      // 64 halves
#define VAL_B   1792                      // 288 rows x 128B, swizzled
#define WHH_B   (VAL_B + SEQ * 128)       // 38656: 192 rows x 128B, swizzled
#define W1_B    (WHH_B + 192 * 128)       // 63232: 32 rows x 128B, swizzled
#define SMEM_BYTES (W1_B + 32 * 128)      // 67328

__global__ __launch_bounds__(NTHR, 3)
void decoder_persist_kernel(const float* __restrict__ xdec,
                            const float* __restrict__ enc,
                            const float* __restrict__ hid,
                            const float* __restrict__ Wih,
                            const float* __restrict__ Whh,
                            const float* __restrict__ bih,
                            const float* __restrict__ bhh,
                            const float* __restrict__ Wk,
                            const float* __restrict__ bk,
                            const float* __restrict__ W1,
                            const float* __restrict__ b1,
                            const float* __restrict__ W2,
                            const float* __restrict__ b2,
                            float* __restrict__ out)
{
    extern __shared__ char smc[];
    float*   sm32 = reinterpret_cast<float*>(smc);
    __half*  xh   = reinterpret_cast<__half*>(smc + XH_B);
    __half*  hh   = reinterpret_cast<__half*>(smc + HH_B);
    __half*  ctxh = reinterpret_cast<__half*>(smc + CTXH_B);
    __half*  valh = reinterpret_cast<__half*>(smc + VAL_B);
    __half*  whhh = reinterpret_cast<__half*>(smc + WHH_B);
    __half*  w1h  = reinterpret_cast<__half*>(smc + W1_B);

    const int tid  = threadIdx.x;
    const int warp = tid >> 5;      // head id in phase C
    const int lane = tid & 31;
    const int b    = blockIdx.x;
    const unsigned FULL = 0xffffffffu;

    // ---- register-resident constants ----
    __half2 wih2[16];               // Wih row cols 0..31 (pad 28..31 = 0), tid<192
    float wk[8];                    // Wk column (lanes 0-7) / bk (lane 8) / 0
    float w28r = 0.f, w28z = 0.f, w28n = 0.f;
    float ba = 0.f, bb = 0.f;       // bih/bhh (tid<192); b1/W2 (warp 6)
    float b2r = 0.f;

    if (tid < 192) {
        const float* wr = Wih + tid * DSZ;
#pragma unroll
        for (int j = 0; j < 14; ++j) wih2[j] = __floats2half2_rn(wr[2*j], wr[2*j+1]);
        wih2[14] = __floats2half2_rn(0.f, 0.f);
        wih2[15] = wih2[14];
        ba = bih[tid]; bb = bhh[tid];
    } else if (warp == 6) {
        ba = b1[lane]; bb = W2[lane]; b2r = b2[0];
    }
#pragma unroll
    for (int d = 0; d < 8; ++d)
        wk[d] = (lane < 8) ? Wk[d * 8 + lane] : ((lane == 8) ? bk[d] : 0.f);
    if (lane < 8) {
        const int i = warp * 8 + lane;
        w28r = Wih[i * DSZ + 28];
        w28z = Wih[(64 + i) * DSZ + 28];
        w28n = Wih[(128 + i) * DSZ + 28];
    }

    // ---- SMEM init ----
    // val: fp16 swizzled rows of 128B
    for (int idx = tid; idx < SEQ * 16; idx += NTHR) {
        int s = idx >> 4, c4 = idx & 15;
        float4 v = reinterpret_cast<const float4*>(enc + ((size_t)s * BS + b) * HID)[c4];
        int hbase = s * 64 + ((((c4 >> 1)) ^ (s & 7)) << 3) + ((c4 & 1) << 2);
        __half2* dst = reinterpret_cast<__half2*>(valh + hbase);
        dst[0] = __floats2half2_rn(v.x, v.y);
        dst[1] = __floats2half2_rn(v.z, v.w);
    }
    // Whh: fp16 swizzled rows of 128B
    for (int idx = tid; idx < 192 * 64; idx += NTHR) {
        int r = idx >> 6, c = idx & 63;
        whhh[r * 64 + (((c >> 3) ^ (r & 7)) << 3) + (c & 7)] = __float2half_rn(Whh[idx]);
    }
    // W1: fp16 swizzled rows of 128B
    for (int idx = tid; idx < 32 * 64; idx += NTHR) {
        int r = idx >> 6, c = idx & 63;
        w1h[r * 64 + (((c >> 3) ^ (r & 7)) << 3) + (c & 7)] = __float2half_rn(W1[idx]);
    }
    if (tid < HID) {
        float hv = hid[(size_t)b * HID + tid];
        sm32[(H32_B >> 2) + tid] = hv;
        hh[tid] = __float2half_rn(hv);
    }
    if (tid < 28) xh[tid] = __float2half_rn(xdec[(size_t)b * (TST + 1) * DSZ + tid]);
    if (tid >= 28 && tid < 32) { xh[tid] = __float2half_rn(0.f); xh[32 + tid] = __float2half_rn(0.f); }
    const float o0 = xdec[(size_t)b * (TST + 1) * DSZ + 28];
    if (tid == 0) sm32[OUTS_B >> 2] = o0;

    float xv_pre = 0.f;
    if (warp == 7 && lane < 28)
        xv_pre = xdec[((size_t)b * (TST + 1) + 1) * DSZ + lane];

    __syncthreads();

#pragma unroll 1
    for (int t = 0; t < TST; ++t) {
        const int cur = t & 1, nxt = cur ^ 1;

        // ======== PHASE A: GRU dots (w0-5) | MLP t-1 (w6) | prefetch (w7) ========
        if (tid < 192) {
            const int g = tid >> 6, j = tid & 63;
            const int sw = tid & 7;
            // h-dot: Whh row (fp16 swizzled) . h (fp16), 4 fp16 accumulators
            __half2 a0 = __floats2half2_rn(0.f, 0.f), a1 = a0, a2 = a0, a3 = a0;
            const char* wrow = smc + WHH_B + tid * 128;
#pragma unroll
            for (int k = 0; k < 8; ++k) {
                uint4 wv = *reinterpret_cast<const uint4*>(wrow + ((k ^ sw) << 4));
                uint4 hv = *reinterpret_cast<const uint4*>(smc + HH_B + (k << 4));
                a0 = __hfma2(u2h2(wv.x), u2h2(hv.x), a0);
                a1 = __hfma2(u2h2(wv.y), u2h2(hv.y), a1);
                a2 = __hfma2(u2h2(wv.z), u2h2(hv.z), a2);
                a3 = __hfma2(u2h2(wv.w), u2h2(hv.w), a3);
            }
            // x-dot: wih2 regs . x (fp16), 2 accumulators
            __half2 x0 = __floats2half2_rn(0.f, 0.f), x1 = x0;
            const char* xrow = smc + XH_B + cur * 64;
#pragma unroll
            for (int k = 0; k < 4; ++k) {
                uint4 xv = *reinterpret_cast<const uint4*>(xrow + (k << 4));
                x0 = __hfma2(wih2[4*k+0], u2h2(xv.x), x0);
                x1 = __hfma2(wih2[4*k+1], u2h2(xv.y), x1);
                x0 = __hfma2(wih2[4*k+2], u2h2(xv.z), x0);
                x1 = __hfma2(wih2[4*k+3], u2h2(xv.w), x1);
            }
            float2 f0 = __half22float2(a0), f1 = __half22float2(a1);
            float2 f2 = __half22float2(a2), f3 = __half22float2(a3);
            float ghs = bb + ((f0.x + f0.y) + (f1.x + f1.y)) + ((f2.x + f2.y) + (f3.x + f3.y));
            float2 g0 = __half22float2(x0), g1 = __half22float2(x1);
            float gxs = ba + (g0.x + g0.y) + (g1.x + g1.y);
            if (g < 2) sm32[(GS_B >> 2) + (g << 6) + j] = gxs + ghs;
            else { sm32[(GXN_B >> 2) + j] = gxs; sm32[(GHN_B >> 2) + j] = ghs; }
        } else if (warp == 6) {
            if (t > 0) {
                // MLP for step t-1: W1 (fp16 swizzled SMEM) . ctx (fp16)
                const int sw = lane & 7;
                const char* wrow = smc + W1_B + lane * 128;
                __half2 a0 = __floats2half2_rn(0.f, 0.f), a1 = a0, a2 = a0, a3 = a0;
#pragma unroll
                for (int k = 0; k < 8; ++k) {
                    uint4 wv = *reinterpret_cast<const uint4*>(wrow + ((k ^ sw) << 4));
                    uint4 cv = *reinterpret_cast<const uint4*>(smc + CTXH_B + (k << 4));
                    a0 = __hfma2(u2h2(wv.x), u2h2(cv.x), a0);
                    a1 = __hfma2(u2h2(wv.y), u2h2(cv.y), a1);
                    a2 = __hfma2(u2h2(wv.z), u2h2(cv.z), a2);
                    a3 = __hfma2(u2h2(wv.w), u2h2(cv.w), a3);
                }
                float2 f0 = __half22float2(a0), f1 = __half22float2(a1);
                float2 f2 = __half22float2(a2), f3 = __half22float2(a3);
                float y = ba + ((f0.x + f0.y) + (f1.x + f1.y)) + ((f2.x + f2.y) + (f3.x + f3.y));
                float p = fmaxf(y, 0.f) * bb;
#pragma unroll
                for (int off = 16; off >= 1; off >>= 1)
                    p += __shfl_xor_sync(FULL, p, off);
                if (lane == 0) {
                    float o = p + b2r;
                    out[(size_t)b * TST + (t - 1)] = o;
                    sm32[OUTS_B >> 2] = o;
                }
            }
        } else if (warp == 7) {
            if (lane < 28) {
                xh[nxt * 32 + lane] = __float2half_rn(xv_pre);
                int row = (t + 2 <= TST) ? (t + 2) : TST;
                xv_pre = xdec[((size_t)b * (TST + 1) + row) * DSZ + lane];
            }
        }
        __syncthreads();

        // ======== PHASE C: gates (lanes<8) + attention (all warps, head=warp) ======
        {
            float hn = 0.f;
            if (lane < 8) {
                const int i = warp * 8 + lane;
                float o  = sm32[OUTS_B >> 2];
                float gr = sm32[(GS_B >> 2) + i]      + w28r * o;
                float gz = sm32[(GS_B >> 2) + 64 + i] + w28z * o;
                float ax = sm32[(GXN_B >> 2) + i]     + w28n * o;
                float ah = sm32[(GHN_B >> 2) + i];
                float r  = 1.f / (1.f + __expf(-gr));
                float z  = 1.f / (1.f + __expf(-gz));
                float a  = ax + r * ah;
                float e2 = __expf(2.f * a);
                float nt = 1.f - 2.f / (e2 + 1.f);
                float hp0 = sm32[(H32_B >> 2) + i];
                hn = nt + z * (hp0 - nt);
                sm32[(H32_B >> 2) + i] = hn;
                hh[i] = __float2half_rn(hn);
            }

            // q' = h_new @ Wk (lanes 0-7), qb = h_new . bk (lane 8)
            float q = 0.f;
#pragma unroll
            for (int d = 0; d < 8; ++d)
                q = fmaf(__shfl_sync(FULL, hn, d), wk[d], q);
            u64 qp2[4];
#pragma unroll
            for (int j = 0; j < 4; ++j)
                qp2[j] = pk2(__shfl_sync(FULL, q, 2 * j), __shfl_sync(FULL, q, 2 * j + 1));
            float qb = __shfl_sync(FULL, q, 8);

            // single-pass attention over swizzled fp16 val
            float w0 = 0.f, w1s = 0.f;
            u64 c2[4] = {0ull, 0ull, 0ull, 0ull};
            const char* vb = smc + VAL_B + ((warp ^ (lane & 7)) << 4) + lane * 128;
#pragma unroll
            for (int i = 0; i < 9; ++i) {
                uint4 vv = *reinterpret_cast<const uint4*>(vb + i * 4096);
                float2 f0 = __half22float2(u2h2(vv.x));
                float2 f1 = __half22float2(u2h2(vv.y));
                float2 f2 = __half22float2(u2h2(vv.z));
                float2 f3 = __half22float2(u2h2(vv.w));
                u64 v0 = pk2(f0.x, f0.y), v1 = pk2(f1.x, f1.y);
                u64 v2 = pk2(f2.x, f2.y), v3 = pk2(f3.x, f3.y);
                u64 acc = ffma2(qp2[0], v0, 0ull);
                acc = ffma2(qp2[1], v1, acc);
                acc = ffma2(qp2[2], v2, acc);
                acc = ffma2(qp2[3], v3, acc);
                float s0, s1; upk2(acc, s0, s1);
                float e = __expf(s0 + s1 + qb);
                if (i & 1) w1s += e; else w0 += e;
                u64 ee = pk2(e, e);
                c2[0] = ffma2(ee, v0, c2[0]);
                c2[1] = ffma2(ee, v1, c2[1]);
                c2[2] = ffma2(ee, v2, c2[2]);
                c2[3] = ffma2(ee, v3, c2[3]);
            }
            float wsum = w0 + w1s;

            // --- 14-shfl value-halving reduction ---
            // off16: keep dims by bit4
            {
                const bool hi = (lane & 16);
                u64 s0 = hi ? c2[0] : c2[2];
                u64 s1 = hi ? c2[1] : c2[3];
                u64 r0 = shfl_u64(s0, 16);
                u64 r1 = shfl_u64(s1, 16);
                u64 k0 = hi ? c2[2] : c2[0];
                u64 k1 = hi ? c2[3] : c2[1];
                c2[0] = fadd2(k0, r0);
                c2[1] = fadd2(k1, r1);
                wsum += __shfl_xor_sync(FULL, wsum, 16);
            }
            // off8: keep u64 by bit3
            {
                const bool hi = (lane & 8);
                u64 s = hi ? c2[0] : c2[1];
                u64 r = shfl_u64(s, 8);
                u64 k = hi ? c2[1] : c2[0];
                c2[0] = fadd2(k, r);
                wsum += __shfl_xor_sync(FULL, wsum, 8);
            }
            // off4: keep float by bit2
            float cv;
            {
                float lo, hi2; upk2(c2[0], lo, hi2);
                const bool hi = (lane & 4);
                float s = hi ? lo : hi2;
                float r = __shfl_xor_sync(FULL, s, 4);
                cv = (hi ? hi2 : lo) + r;
                wsum += __shfl_xor_sync(FULL, wsum, 4);
            }
            cv   += __shfl_xor_sync(FULL, cv, 2);
            wsum += __shfl_xor_sync(FULL, wsum, 2);
            cv   += __shfl_xor_sync(FULL, cv, 1);
            wsum += __shfl_xor_sync(FULL, wsum, 1);
            if ((lane & 3) == 0)
                ctxh[warp * 8 + (lane >> 2)] = __float2half_rn(cv * (1.f / wsum));
        }
        __syncthreads();
    }

    // final output MLP (step TST-1)
    if (warp == 6) {
        const int sw = lane & 7;
        const char* wrow = smc + W1_B + lane * 128;
        __half2 a0 = __floats2half2_rn(0.f, 0.f), a1 = a0, a2 = a0, a3 = a0;
#pragma unroll
        for (int k = 0; k < 8; ++k) {
            uint4 wv = *reinterpret_cast<const uint4*>(wrow + ((k ^ sw) << 4));
            uint4 cv = *reinterpret_cast<const uint4*>(smc + CTXH_B + (k << 4));
            a0 = __hfma2(u2h2(wv.x), u2h2(cv.x), a0);
            a1 = __hfma2(u2h2(wv.y), u2h2(cv.y), a1);
            a2 = __hfma2(u2h2(wv.z), u2h2(cv.z), a2);
            a3 = __hfma2(u2h2(wv.w), u2h2(cv.w), a3);
        }
        float2 f0 = __half22float2(a0), f1 = __half22float2(a1);
        float2 f2 = __half22float2(a2), f3 = __half22float2(a3);
        float y = ba + ((f0.x + f0.y) + (f1.x + f1.y)) + ((f2.x + f2.y) + (f3.x + f3.y));
        float p = fmaxf(y, 0.f) * bb;
#pragma unroll
        for (int off = 16; off >= 1; off >>= 1)
            p += __shfl_xor_sync(FULL, p, off);
        if (lane == 0)
            out[(size_t)b * TST + (TST - 1)] = p + b2r;
    }
}

extern "C" void kernel_launch(void* const* d_in, const int* in_sizes, int n_in,
                              void* d_out, int out_size)
{
    const float* xdec = (const float*)d_in[0];
    const float* enc  = (const float*)d_in[1];
    const float* hidp = (const float*)d_in[2];
    const float* Wih  = (const float*)d_in[3];
    const float* Whh  = (const float*)d_in[4];
    const float* bih  = (const float*)d_in[5];
    const float* bhh  = (const float*)d_in[6];
    const float* Wk   = (const float*)d_in[7];
    const float* bk   = (const float*)d_in[8];
    const float* W1   = (const float*)d_in[9];
    const float* b1   = (const float*)d_in[10];
    const float* W2   = (const float*)d_in[11];
    const float* b2   = (const float*)d_in[12];
    float* out = (float*)d_out;

    cudaFuncSetAttribute(decoder_persist_kernel,
                         cudaFuncAttributeMaxDynamicSharedMemorySize, SMEM_BYTES);
    decoder_persist_kernel<<<BS, NTHR, SMEM_BYTES>>>(xdec, enc, hidp, Wih, Whh, bih, bhh,
                                                     Wk, bk, W1, b1, W2, b2, out);
}